// round 4
// baseline (speedup 1.0000x reference)
#include <cuda_runtime.h>

#define TT   2048
#define CC   768
#define NHH  12
#define HS   64
#define C3   2304
#define NSI  255
#define BHC  96
#define NCHUNK 16

__device__ float g_qkv[(size_t)8*TT*C3];
__device__ float g_v  [(size_t)BHC*TT*HS];
__device__ float g_kc [(size_t)BHC*TT*HS];
__device__ float g_vc [(size_t)BHC*TT*HS];
__device__ float g_part[2*BHC*NCHUNK*HS];
__device__ float g_Ki[(size_t)BHC*NSI*HS];
__device__ float g_Vi[(size_t)BHC*NSI*HS];
__device__ float g_att[(size_t)8*TT*CC];

__device__ __forceinline__ void interval_of(int s, int& l, int& r) {
    int base = 0, L = 16, n = TT / 16;
    while (s >= base + n) { base += n; n >>= 1; L <<= 1; }
    int i = s - base;
    l = i * L; r = l + L - 1;
}

// C[M][N] = A[M][K] * B[N][K]^T   (128x128 tile, 256 thr, 8x8 micro)
__global__ __launch_bounds__(256) void sgemm_tn(
    const float* __restrict__ A, const float* __restrict__ B,
    float* __restrict__ C, int M, int N, int K)
{
    __shared__ float As[16][132];
    __shared__ float Bs[16][132];
    const int tid = threadIdx.x;
    const int tx = tid & 15, ty = tid >> 4;
    const int bm = blockIdx.y << 7, bn = blockIdx.x << 7;
    const int lr = tid >> 2, lc = (tid & 3) << 2;

    const float* Ap = A + (size_t)(bm + lr) * K + lc;
    const float* Bp = B + (size_t)(bn + lr) * K + lc;
    float4 pa0 = *(const float4*)(Ap);
    float4 pa1 = *(const float4*)(Ap + (size_t)64 * K);
    float4 pb0 = *(const float4*)(Bp);
    float4 pb1 = *(const float4*)(Bp + (size_t)64 * K);

    float c[8][8];
#pragma unroll
    for (int i = 0; i < 8; i++)
#pragma unroll
        for (int j = 0; j < 8; j++) c[i][j] = 0.f;

    const int nt = K >> 4;
    for (int kt = 0; kt < nt; kt++) {
        As[lc+0][lr]=pa0.x; As[lc+1][lr]=pa0.y; As[lc+2][lr]=pa0.z; As[lc+3][lr]=pa0.w;
        As[lc+0][lr+64]=pa1.x; As[lc+1][lr+64]=pa1.y; As[lc+2][lr+64]=pa1.z; As[lc+3][lr+64]=pa1.w;
        Bs[lc+0][lr]=pb0.x; Bs[lc+1][lr]=pb0.y; Bs[lc+2][lr]=pb0.z; Bs[lc+3][lr]=pb0.w;
        Bs[lc+0][lr+64]=pb1.x; Bs[lc+1][lr+64]=pb1.y; Bs[lc+2][lr+64]=pb1.z; Bs[lc+3][lr+64]=pb1.w;
        __syncthreads();
        if (kt + 1 < nt) {
            const float* Ap2 = Ap + (size_t)(kt + 1) * 16;
            const float* Bp2 = Bp + (size_t)(kt + 1) * 16;
            pa0 = *(const float4*)(Ap2);
            pa1 = *(const float4*)(Ap2 + (size_t)64 * K);
            pb0 = *(const float4*)(Bp2);
            pb1 = *(const float4*)(Bp2 + (size_t)64 * K);
        }
#pragma unroll
        for (int kk = 0; kk < 16; kk++) {
            float4 xa0 = *(const float4*)(&As[kk][ty*4]);
            float4 xa1 = *(const float4*)(&As[kk][ty*4 + 64]);
            float4 xb0 = *(const float4*)(&Bs[kk][tx*4]);
            float4 xb1 = *(const float4*)(&Bs[kk][tx*4 + 64]);
            float av[8] = {xa0.x,xa0.y,xa0.z,xa0.w, xa1.x,xa1.y,xa1.z,xa1.w};
            float bw[8] = {xb0.x,xb0.y,xb0.z,xb0.w, xb1.x,xb1.y,xb1.z,xb1.w};
#pragma unroll
            for (int i = 0; i < 8; i++)
#pragma unroll
                for (int j = 0; j < 8; j++) c[i][j] += av[i] * bw[j];
        }
        __syncthreads();
    }
#pragma unroll
    for (int i = 0; i < 8; i++) {
        int row = bm + ((i < 4) ? (ty*4 + i) : (64 + ty*4 + i - 4));
        *(float4*)(C + (size_t)row*N + bn + tx*4)      = make_float4(c[i][0],c[i][1],c[i][2],c[i][3]);
        *(float4*)(C + (size_t)row*N + bn + 64 + tx*4) = make_float4(c[i][4],c[i][5],c[i][6],c[i][7]);
    }
}

// v[t,e] = sum_i k[t,i] * (sum_j v0[t,j] * Wv[e, i*64+j]) + bv[e]
__global__ __launch_bounds__(256) void veinsum_kernel(
    const float* __restrict__ Wv, const float* __restrict__ bv)
{
    extern __shared__ float sm[];
    float* ks  = sm;              // [128][64]
    float* v0s = sm + 128*64;     // [128][64]
    float* ws0 = sm + 2*128*64;   // [64][65]
    float* ws1 = ws0 + 64*65;

    const int tid = threadIdx.x;
    const int b = blockIdx.z, h = blockIdx.y;
    const int t0 = blockIdx.x << 7;
    const int lrow = tid >> 4, lcol = (tid & 15) << 2;
    const int tx = tid & 15, ty = tid >> 4;

    const float* kbase = g_qkv + ((size_t)(b*TT + t0))*C3 + CC + h*HS;
#pragma unroll
    for (int it = 0; it < 8; it++) {
        int row = lrow + (it << 4);
        *(float4*)(ks  + row*64 + lcol) = *(const float4*)(kbase + (size_t)row*C3 + lcol);
        *(float4*)(v0s + row*64 + lcol) = *(const float4*)(kbase + (size_t)row*C3 + CC + lcol);
    }
    float4 w[4];
#pragma unroll
    for (int q = 0; q < 4; q++)
        w[q] = *(const float4*)(Wv + (size_t)(lrow + q*16)*4096 + lcol);
#pragma unroll
    for (int q = 0; q < 4; q++) {
        float* dst = ws0 + (lrow + q*16)*65 + lcol;
        dst[0]=w[q].x; dst[1]=w[q].y; dst[2]=w[q].z; dst[3]=w[q].w;
    }
    __syncthreads();

    float c[8][4];
#pragma unroll
    for (int t2 = 0; t2 < 8; t2++)
#pragma unroll
        for (int q = 0; q < 4; q++) c[t2][q] = 0.f;

    for (int i = 0; i < 64; i++) {
        float* wcur  = (i & 1) ? ws1 : ws0;
        float* wnext = (i & 1) ? ws0 : ws1;
        if (i + 1 < 64) {
#pragma unroll
            for (int q = 0; q < 4; q++)
                w[q] = *(const float4*)(Wv + (size_t)(lrow + q*16)*4096 + (i+1)*64 + lcol);
        }
        float d[8][4];
#pragma unroll
        for (int t2 = 0; t2 < 8; t2++)
#pragma unroll
            for (int q = 0; q < 4; q++) d[t2][q] = 0.f;
#pragma unroll 16
        for (int j = 0; j < 64; j++) {
            float a[8];
#pragma unroll
            for (int t2 = 0; t2 < 8; t2++) a[t2] = v0s[(ty*8 + t2)*64 + j];
            float bb[4];
#pragma unroll
            for (int q = 0; q < 4; q++) bb[q] = wcur[(tx*4 + q)*65 + j];
#pragma unroll
            for (int t2 = 0; t2 < 8; t2++)
#pragma unroll
                for (int q = 0; q < 4; q++) d[t2][q] += a[t2] * bb[q];
        }
#pragma unroll
        for (int t2 = 0; t2 < 8; t2++) {
            float kk = ks[(ty*8 + t2)*64 + i];
#pragma unroll
            for (int q = 0; q < 4; q++) c[t2][q] += kk * d[t2][q];
        }
        if (i + 1 < 64) {
#pragma unroll
            for (int q = 0; q < 4; q++) {
                float* dst = wnext + (lrow + q*16)*65 + lcol;
                dst[0]=w[q].x; dst[1]=w[q].y; dst[2]=w[q].z; dst[3]=w[q].w;
            }
        }
        __syncthreads();
    }

    float4 bvv = *(const float4*)(bv + tx*4);
    float* vout = g_v + ((size_t)(b*NHH + h)*TT + t0)*HS;
#pragma unroll
    for (int t2 = 0; t2 < 8; t2++) {
        int row = ty*8 + t2;
        *(float4*)(vout + (size_t)row*HS + tx*4) =
            make_float4(c[t2][0]+bvv.x, c[t2][1]+bvv.y, c[t2][2]+bvv.z, c[t2][3]+bvv.w);
    }
}

__global__ void cumsum_partial() {
    int chunk = blockIdx.x, bh = blockIdx.y, which = blockIdx.z;
    int d = threadIdx.x;
    int b = bh / NHH, h = bh - b*NHH;
    float s = 0.f;
    if (which == 0) {
        const float* p = g_qkv + ((size_t)(b*TT + (chunk<<7)))*C3 + CC + h*HS + d;
#pragma unroll 4
        for (int t2 = 0; t2 < 128; t2++) s += p[(size_t)t2*C3];
    } else {
        const float* p = g_v + ((size_t)bh*TT + (chunk<<7))*HS + d;
#pragma unroll 4
        for (int t2 = 0; t2 < 128; t2++) s += p[t2*HS];
    }
    g_part[((size_t)(which*BHC + bh)*NCHUNK + chunk)*HS + d] = s;
}

__global__ void cumsum_scanpart() {
    int bh = blockIdx.x, which = blockIdx.y;
    int d = threadIdx.x;
    float run = 0.f;
    for (int c = 0; c < NCHUNK; c++) {
        size_t idx = ((size_t)(which*BHC + bh)*NCHUNK + c)*HS + d;
        float xv = g_part[idx];
        g_part[idx] = run;
        run += xv;
    }
}

__global__ void cumsum_final() {
    int chunk = blockIdx.x, bh = blockIdx.y, which = blockIdx.z;
    int d = threadIdx.x;
    int b = bh / NHH, h = bh - b*NHH;
    float run = g_part[((size_t)(which*BHC + bh)*NCHUNK + chunk)*HS + d];
    float* outp = (which ? g_vc : g_kc) + ((size_t)bh*TT + (chunk<<7))*HS + d;
    if (which == 0) {
        const float* p = g_qkv + ((size_t)(b*TT + (chunk<<7)))*C3 + CC + h*HS + d;
#pragma unroll 4
        for (int t2 = 0; t2 < 128; t2++) { run += p[(size_t)t2*C3]; outp[(size_t)t2*HS] = run; }
    } else {
        const float* p = g_v + ((size_t)bh*TT + (chunk<<7))*HS + d;
#pragma unroll 4
        for (int t2 = 0; t2 < 128; t2++) { run += p[t2*HS]; outp[(size_t)t2*HS] = run; }
    }
}

__global__ void slices_kernel() {
    int bh = blockIdx.x;
    const float* kcb = g_kc + (size_t)bh*TT*HS;
    const float* vcb = g_vc + (size_t)bh*TT*HS;
    for (int idx = threadIdx.x; idx < NSI*HS; idx += 256) {
        int s = idx / HS, d = idx - s*HS;
        int l, r; interval_of(s, l, r);
        float kv = kcb[(size_t)r*HS + d];
        float vv = vcb[(size_t)r*HS + d];
        if (l > 0) { kv -= kcb[(size_t)(l-1)*HS + d]; vv -= vcb[(size_t)(l-1)*HS + d]; }
        g_Ki[(size_t)bh*NSI*HS + idx] = kv;
        g_Vi[(size_t)bh*NSI*HS + idx] = vv;
    }
}

__global__ __launch_bounds__(256) void attention_kernel() {
    extern __shared__ float sm[];
    float* Ks = sm;
    float* Vs = sm + NSI*HS;
    const int bh = blockIdx.y;
    const int b = bh / NHH, h = bh - b*NHH;
    const int tid = threadIdx.x;
    const int t = (blockIdx.x << 8) + tid;

    const float* Kgb = g_Ki + (size_t)bh*NSI*HS;
    const float* Vgb = g_Vi + (size_t)bh*NSI*HS;
    for (int idx = tid*4; idx < NSI*HS; idx += 1024) {
        *(float4*)(Ks + idx) = *(const float4*)(Kgb + idx);
        *(float4*)(Vs + idx) = *(const float4*)(Vgb + idx);
    }
    __syncthreads();

    float q[64];
    const float* qp = g_qkv + ((size_t)(b*TT + t))*C3 + h*HS;
#pragma unroll
    for (int d4 = 0; d4 < 16; d4++) {
        float4 qq = *(const float4*)(qp + d4*4);
        q[d4*4+0]=qq.x; q[d4*4+1]=qq.y; q[d4*4+2]=qq.z; q[d4*4+3]=qq.w;
    }
    float out[64];
#pragma unroll
    for (int d = 0; d < 64; d++) out[d] = 0.f;
    float m = -1e30f, ssum = 0.f;
    const float scale = 0.125f;
    const int twmax = t | 31;

    int sbase = 0;
#pragma unroll 1
    for (int lev = 0; lev < 8; lev++) {
        const int lsh = 4 + lev;
        const int n = TT >> lsh;
        int imaxw = (twmax + 1) >> lsh;
        if (imaxw > n) imaxw = n;
        for (int i = 0; i < imaxw; i++) {
            const int s = sbase + i;
            const int r = ((i + 1) << lsh) - 1;
            const float* Kr = Ks + s*HS;
            float a0=0.f, a1=0.f, a2=0.f, a3=0.f;
#pragma unroll
            for (int d4 = 0; d4 < 16; d4++) {
                float4 kv = *(const float4*)(Kr + d4*4);
                a0 += q[d4*4+0]*kv.x; a1 += q[d4*4+1]*kv.y;
                a2 += q[d4*4+2]*kv.z; a3 += q[d4*4+3]*kv.w;
            }
            float x = (a0+a1+a2+a3) * scale;
            if (t >= r) {
                const float* Vr = Vs + s*HS;
                if (x > m) {
                    float f = __expf(m - x);
                    ssum = ssum * f + 1.f;
                    m = x;
#pragma unroll
                    for (int d4 = 0; d4 < 16; d4++) {
                        float4 vv = *(const float4*)(Vr + d4*4);
                        out[d4*4+0] = out[d4*4+0]*f + vv.x;
                        out[d4*4+1] = out[d4*4+1]*f + vv.y;
                        out[d4*4+2] = out[d4*4+2]*f + vv.z;
                        out[d4*4+3] = out[d4*4+3]*f + vv.w;
                    }
                } else {
                    float wgt = __expf(x - m);
                    ssum += wgt;
#pragma unroll
                    for (int d4 = 0; d4 < 16; d4++) {
                        float4 vv = *(const float4*)(Vr + d4*4);
                        out[d4*4+0] += wgt*vv.x; out[d4*4+1] += wgt*vv.y;
                        out[d4*4+2] += wgt*vv.z; out[d4*4+3] += wgt*vv.w;
                    }
                }
            }
        }
        sbase += n;
    }

    const int lt = t & ~15;
    const bool hasl = lt > 0;
    const float* kr = g_kc + ((size_t)bh*TT + t)*HS;
    const float* kl = g_kc + ((size_t)bh*TT + (hasl ? lt-1 : 0))*HS;
    const float* vr = g_vc + ((size_t)bh*TT + t)*HS;
    const float* vl = g_vc + ((size_t)bh*TT + (hasl ? lt-1 : 0))*HS;
    float a0=0.f, a1=0.f, a2=0.f, a3=0.f;
#pragma unroll
    for (int d4 = 0; d4 < 16; d4++) {
        float4 kv = *(const float4*)(kr + d4*4);
        float4 klv = hasl ? *(const float4*)(kl + d4*4) : make_float4(0.f,0.f,0.f,0.f);
        a0 += q[d4*4+0]*(kv.x-klv.x); a1 += q[d4*4+1]*(kv.y-klv.y);
        a2 += q[d4*4+2]*(kv.z-klv.z); a3 += q[d4*4+3]*(kv.w-klv.w);
    }
    float xt = (a0+a1+a2+a3) * scale;
    if (xt > m) {
        float f = __expf(m - xt);
        ssum = ssum * f + 1.f;
        m = xt;
#pragma unroll
        for (int d4 = 0; d4 < 16; d4++) {
            float4 vv = *(const float4*)(vr + d4*4);
            float4 vlv = hasl ? *(const float4*)(vl + d4*4) : make_float4(0.f,0.f,0.f,0.f);
            out[d4*4+0] = out[d4*4+0]*f + (vv.x-vlv.x);
            out[d4*4+1] = out[d4*4+1]*f + (vv.y-vlv.y);
            out[d4*4+2] = out[d4*4+2]*f + (vv.z-vlv.z);
            out[d4*4+3] = out[d4*4+3]*f + (vv.w-vlv.w);
        }
    } else {
        float wgt = __expf(xt - m);
        ssum += wgt;
#pragma unroll
        for (int d4 = 0; d4 < 16; d4++) {
            float4 vv = *(const float4*)(vr + d4*4);
            float4 vlv = hasl ? *(const float4*)(vl + d4*4) : make_float4(0.f,0.f,0.f,0.f);
            out[d4*4+0] += wgt*(vv.x-vlv.x); out[d4*4+1] += wgt*(vv.y-vlv.y);
            out[d4*4+2] += wgt*(vv.z-vlv.z); out[d4*4+3] += wgt*(vv.w-vlv.w);
        }
    }

    float inv = 1.f / ssum;
    float* op = g_att + ((size_t)(b*TT + t))*CC + h*HS;
#pragma unroll
    for (int d4 = 0; d4 < 16; d4++) {
        *(float4*)(op + d4*4) = make_float4(out[d4*4+0]*inv, out[d4*4+1]*inv,
                                            out[d4*4+2]*inv, out[d4*4+3]*inv);
    }
}

extern "C" void kernel_launch(void* const* d_in, const int* in_sizes, int n_in,
                              void* d_out, int out_size) {
    (void)in_sizes; (void)n_in; (void)out_size;
    const float* x     = (const float*)d_in[0];
    const float* Wqkv  = (const float*)d_in[1];
    const float* Wproj = (const float*)d_in[2];
    const float* Wv    = (const float*)d_in[3];
    const float* bv    = (const float*)d_in[4];
    float* out = (float*)d_out;

    static bool attr_set = false;
    if (!attr_set) {
        cudaFuncSetAttribute(veinsum_kernel,
            cudaFuncAttributeMaxDynamicSharedMemorySize, 98816);
        cudaFuncSetAttribute(attention_kernel,
            cudaFuncAttributeMaxDynamicSharedMemorySize, 130560);
        attr_set = true;
    }

    float* qkv;  cudaGetSymbolAddress((void**)&qkv, g_qkv);
    float* gatt; cudaGetSymbolAddress((void**)&gatt, g_att);

    // 1. QKV GEMM: (16384,768) @ (2304,768)^T -> (16384,2304)
    sgemm_tn<<<dim3(18, 128), 256>>>(x, Wqkv, qkv, 16384, 2304, 768);

    // 2. v einsum
    veinsum_kernel<<<dim3(16, 12, 8), 256, 98816>>>(Wv, bv);

    // 3. cumsum (k from qkv, v from g_v)
    cumsum_partial <<<dim3(NCHUNK, BHC, 2), 64>>>();
    cumsum_scanpart<<<dim3(BHC, 2), 64>>>();
    cumsum_final   <<<dim3(NCHUNK, BHC, 2), 64>>>();

    // 4. interval slices
    slices_kernel<<<BHC, 256>>>();

    // 5. attention
    attention_kernel<<<dim3(8, BHC), 256, 130560>>>();

    // 6. output projection: (16384,768) @ (768,768)^T -> (16384,768)
    sgemm_tn<<<dim3(6, 128), 256>>>(gatt, Wproj, out, 16384, 768, 768);
}

// round 5
// speedup vs baseline: 2.2958x; 2.2958x over previous
#include <cuda_runtime.h>
#include <cuda_bf16.h>

#define TT   2048
#define CC   768
#define NHH  12
#define HS   64
#define C3   2304
#define NSI  255
#define BHC  96
#define NCHUNK 16

__device__ float g_qkv[(size_t)8*TT*C3];
__device__ float g_v  [(size_t)BHC*TT*HS];
__device__ float g_kc [(size_t)BHC*TT*HS];
__device__ float g_vc [(size_t)BHC*TT*HS];
__device__ float g_part[2*BHC*NCHUNK*HS];
__device__ float g_Ki[(size_t)BHC*NSI*HS];
__device__ float g_Vi[(size_t)BHC*NSI*HS];
__device__ float g_att[(size_t)8*TT*CC];
__device__ __nv_bfloat16 g_Wvh[HS*4096];
__device__ __nv_bfloat16 g_Wvl[HS*4096];

__device__ __forceinline__ void interval_of(int s, int& l, int& r) {
    int base = 0, L = 16, n = TT / 16;
    while (s >= base + n) { base += n; n >>= 1; L <<= 1; }
    int i = s - base;
    l = i * L; r = l + L - 1;
}

__device__ __forceinline__ void mma16816(float* c, const unsigned* a, const unsigned* b) {
    asm volatile(
        "mma.sync.aligned.m16n8k16.row.col.f32.bf16.bf16.f32 "
        "{%0,%1,%2,%3}, {%4,%5,%6,%7}, {%8,%9}, {%0,%1,%2,%3};\n"
        : "+f"(c[0]), "+f"(c[1]), "+f"(c[2]), "+f"(c[3])
        : "r"(a[0]), "r"(a[1]), "r"(a[2]), "r"(a[3]), "r"(b[0]), "r"(b[1]));
}

__device__ __forceinline__ unsigned pk2(float a, float b,
                                        __nv_bfloat16& la, __nv_bfloat16& lb) {
    __nv_bfloat16 ha = __float2bfloat16(a);
    __nv_bfloat16 hb = __float2bfloat16(b);
    la = __float2bfloat16(a - __bfloat162float(ha));
    lb = __float2bfloat16(b - __bfloat162float(hb));
    __nv_bfloat162 t; t.x = ha; t.y = hb;
    return *(unsigned*)&t;
}
__device__ __forceinline__ unsigned pkl(__nv_bfloat16 a, __nv_bfloat16 b) {
    __nv_bfloat162 t; t.x = a; t.y = b;
    return *(unsigned*)&t;
}

// ------------- split Wv into bf16 hi/lo (once per call, tiny) --------------
__global__ void wvsplit_kernel(const float* __restrict__ Wv) {
    int idx = blockIdx.x * 256 + threadIdx.x;
    float v = Wv[idx];
    __nv_bfloat16 h = __float2bfloat16(v);
    g_Wvh[idx] = h;
    g_Wvl[idx] = __float2bfloat16(v - __bfloat162float(h));
}

// ------------- C[M][N] = A[M][K] @ B[N][K]^T, fp32 io, 3x bf16 mma ---------
// 128x128 tile, 256 threads, 8 warps as 2(m) x 4(n), warp tile 64x32.
#define SA 40
__global__ __launch_bounds__(256, 1) void gemm_tn_mma(
    const float* __restrict__ A, const float* __restrict__ B,
    float* __restrict__ C, int M, int N, int K)
{
    __shared__ __nv_bfloat16 sAh[128*SA], sAl[128*SA];
    __shared__ __nv_bfloat16 sBh[128*SA], sBl[128*SA];
    const int tid = threadIdx.x;
    const int bm = blockIdx.y << 7, bn = blockIdx.x << 7;
    const int lr = tid >> 3;            // 0..31
    const int lk = (tid & 7) << 2;      // 0..28
    const int warpid = tid >> 5, lane = tid & 31;
    const int wm = (warpid >> 2) << 6;  // 0 / 64
    const int wn = (warpid & 3) << 5;   // 0..96
    const int gm = lane >> 2, kp = (lane & 3) << 1;

    float4 pa[4], pb[4];
#pragma unroll
    for (int p = 0; p < 4; p++) {
        pa[p] = *(const float4*)(A + (size_t)(bm + lr + p*32)*K + lk);
        pb[p] = *(const float4*)(B + (size_t)(bn + lr + p*32)*K + lk);
    }

    float acc[16][4];
#pragma unroll
    for (int i = 0; i < 16; i++)
#pragma unroll
        for (int j = 0; j < 4; j++) acc[i][j] = 0.f;

    const int nt = K >> 5;
    for (int kt = 0; kt < nt; kt++) {
#pragma unroll
        for (int p = 0; p < 4; p++) {
            int ro = (lr + p*32)*SA + lk;
            __nv_bfloat16 l0, l1, l2, l3;
            unsigned h01 = pk2(pa[p].x, pa[p].y, l0, l1);
            unsigned h23 = pk2(pa[p].z, pa[p].w, l2, l3);
            *(unsigned*)(sAh + ro)     = h01;
            *(unsigned*)(sAh + ro + 2) = h23;
            *(unsigned*)(sAl + ro)     = pkl(l0, l1);
            *(unsigned*)(sAl + ro + 2) = pkl(l2, l3);
            h01 = pk2(pb[p].x, pb[p].y, l0, l1);
            h23 = pk2(pb[p].z, pb[p].w, l2, l3);
            *(unsigned*)(sBh + ro)     = h01;
            *(unsigned*)(sBh + ro + 2) = h23;
            *(unsigned*)(sBl + ro)     = pkl(l0, l1);
            *(unsigned*)(sBl + ro + 2) = pkl(l2, l3);
        }
        __syncthreads();
        if (kt + 1 < nt) {
            const float* Ap = A + (size_t)(kt + 1) * 32 + lk;
            const float* Bp = B + (size_t)(kt + 1) * 32 + lk;
#pragma unroll
            for (int p = 0; p < 4; p++) {
                pa[p] = *(const float4*)(Ap + (size_t)(bm + lr + p*32)*K);
                pb[p] = *(const float4*)(Bp + (size_t)(bn + lr + p*32)*K);
            }
        }
#pragma unroll
        for (int ks = 0; ks < 2; ks++) {
            const int k0 = ks << 4;
            unsigned ah[4][4], al[4][4], bh[4][2], bl[4][2];
#pragma unroll
            for (int mt = 0; mt < 4; mt++) {
                const __nv_bfloat16* p0 = sAh + (wm + mt*16 + gm)*SA + k0 + kp;
                const __nv_bfloat16* p1 = sAl + (wm + mt*16 + gm)*SA + k0 + kp;
                ah[mt][0] = *(const unsigned*)(p0);
                ah[mt][1] = *(const unsigned*)(p0 + 8*SA);
                ah[mt][2] = *(const unsigned*)(p0 + 8);
                ah[mt][3] = *(const unsigned*)(p0 + 8*SA + 8);
                al[mt][0] = *(const unsigned*)(p1);
                al[mt][1] = *(const unsigned*)(p1 + 8*SA);
                al[mt][2] = *(const unsigned*)(p1 + 8);
                al[mt][3] = *(const unsigned*)(p1 + 8*SA + 8);
            }
#pragma unroll
            for (int ntl = 0; ntl < 4; ntl++) {
                const __nv_bfloat16* p0 = sBh + (wn + ntl*8 + gm)*SA + k0 + kp;
                const __nv_bfloat16* p1 = sBl + (wn + ntl*8 + gm)*SA + k0 + kp;
                bh[ntl][0] = *(const unsigned*)(p0);
                bh[ntl][1] = *(const unsigned*)(p0 + 8);
                bl[ntl][0] = *(const unsigned*)(p1);
                bl[ntl][1] = *(const unsigned*)(p1 + 8);
            }
#pragma unroll
            for (int mt = 0; mt < 4; mt++)
#pragma unroll
                for (int ntl = 0; ntl < 4; ntl++) {
                    float* cp = acc[mt*4 + ntl];
                    mma16816(cp, ah[mt], bh[ntl]);
                    mma16816(cp, ah[mt], bl[ntl]);
                    mma16816(cp, al[mt], bh[ntl]);
                }
        }
        __syncthreads();
    }

#pragma unroll
    for (int mt = 0; mt < 4; mt++) {
        int row = bm + wm + mt*16 + gm;
        int col = bn + wn + (lane & 3)*2;
#pragma unroll
        for (int ntl = 0; ntl < 4; ntl++) {
            float* cp = acc[mt*4 + ntl];
            *(float2*)(C + (size_t)row*N + col + ntl*8)       = make_float2(cp[0], cp[1]);
            *(float2*)(C + (size_t)(row + 8)*N + col + ntl*8) = make_float2(cp[2], cp[3]);
        }
    }
}

// ------------- fused v-einsum: v[t,e] = sum_i k[t,i]*(v0[t,:]@Wv_i^T)[e]+bv
// block: (mtile of 128 tokens, bh). 8 warps as 4(m) x 2(n), warp tile 32x32.
#define SV 72
#define SKP 65
__global__ __launch_bounds__(256, 1) void veinsum_mma(const float* __restrict__ bv) {
    extern __shared__ char smraw[];
    float*         sk  = (float*)smraw;                       // [128][65]
    __nv_bfloat16* v0h = (__nv_bfloat16*)(smraw + 33280);     // [128][72]
    __nv_bfloat16* v0l = (__nv_bfloat16*)(smraw + 33280 + 18432);
    __nv_bfloat16* sB  = (__nv_bfloat16*)(smraw + 70144);     // h0,h1,l0,l1 each [64][72]

    const int tid = threadIdx.x;
    const int bh = blockIdx.y;
    const int b = bh / NHH, h = bh - b*NHH;
    const int t0 = blockIdx.x << 7;
    const int warpid = tid >> 5, lane = tid & 31;
    const int wm = (warpid >> 1) << 5;   // 0..96
    const int wn = (warpid & 1) << 5;    // 0 / 32
    const int gm = lane >> 2, kp = (lane & 3) << 1;

    // load k (fp32) and v0 (split) tiles
    const float* kbase = g_qkv + ((size_t)(b*TT + t0))*C3 + CC + h*HS;
    {
        int r = tid >> 4, c4 = (tid & 15) << 2;
#pragma unroll
        for (int p = 0; p < 8; p++) {
            int row = r + p*16;
            float4 kv = *(const float4*)(kbase + (size_t)row*C3 + c4);
            sk[row*SKP + c4+0] = kv.x; sk[row*SKP + c4+1] = kv.y;
            sk[row*SKP + c4+2] = kv.z; sk[row*SKP + c4+3] = kv.w;
            float4 vv = *(const float4*)(kbase + (size_t)row*C3 + CC + c4);
            __nv_bfloat16 l0, l1, l2, l3;
            unsigned h01 = pk2(vv.x, vv.y, l0, l1);
            unsigned h23 = pk2(vv.z, vv.w, l2, l3);
            int ro = row*SV + c4;
            *(unsigned*)(v0h + ro)     = h01;
            *(unsigned*)(v0h + ro + 2) = h23;
            *(unsigned*)(v0l + ro)     = pkl(l0, l1);
            *(unsigned*)(v0l + ro + 2) = pkl(l2, l3);
        }
    }
    // prefetch B(i=0): Wvh/Wvl [64][4096], tile rows e=0..63, cols 0..63
    const int bs = tid, be = bs >> 3, bq = bs & 7;          // slot 0..255: e=bs>>3? need 512 slots
    uint4 pbh[2], pbl[2];
#pragma unroll
    for (int p = 0; p < 2; p++) {
        int slot = tid + p*256;            // 0..511
        int e = slot >> 3, q = slot & 7;
        pbh[p] = *(const uint4*)(g_Wvh + (size_t)e*4096 + q*8);
        pbl[p] = *(const uint4*)(g_Wvl + (size_t)e*4096 + q*8);
    }
    __syncthreads();

    // hoist v0 fragments for all 4 k-steps
    unsigned vh[4][2][4], vl[4][2][4];
#pragma unroll
    for (int ks = 0; ks < 4; ks++) {
        int k0 = ks << 4;
#pragma unroll
        for (int mt = 0; mt < 2; mt++) {
            const __nv_bfloat16* p0 = v0h + (wm + mt*16 + gm)*SV + k0 + kp;
            const __nv_bfloat16* p1 = v0l + (wm + mt*16 + gm)*SV + k0 + kp;
            vh[ks][mt][0] = *(const unsigned*)(p0);
            vh[ks][mt][1] = *(const unsigned*)(p0 + 8*SV);
            vh[ks][mt][2] = *(const unsigned*)(p0 + 8);
            vh[ks][mt][3] = *(const unsigned*)(p0 + 8*SV + 8);
            vl[ks][mt][0] = *(const unsigned*)(p1);
            vl[ks][mt][1] = *(const unsigned*)(p1 + 8*SV);
            vl[ks][mt][2] = *(const unsigned*)(p1 + 8);
            vl[ks][mt][3] = *(const unsigned*)(p1 + 8*SV + 8);
        }
    }

    float acc[2][4][4];
#pragma unroll
    for (int mt = 0; mt < 2; mt++)
#pragma unroll
        for (int ntl = 0; ntl < 4; ntl++)
#pragma unroll
            for (int j = 0; j < 4; j++) acc[mt][ntl][j] = 0.f;

    // store B(0) into buffer 0
    {
        __nv_bfloat16* dBh = sB;                  // [64][72]
        __nv_bfloat16* dBl = sB + 2*64*SV;
#pragma unroll
        for (int p = 0; p < 2; p++) {
            int slot = tid + p*256;
            int e = slot >> 3, q = slot & 7;
            *(uint4*)(dBh + e*SV + q*8) = pbh[p];
            *(uint4*)(dBl + e*SV + q*8) = pbl[p];
        }
    }
    __syncthreads();

    for (int i = 0; i < 64; i++) {
        int cur = i & 1, nxt = cur ^ 1;
        if (i + 1 < 64) {
#pragma unroll
            for (int p = 0; p < 2; p++) {
                int slot = tid + p*256;
                int e = slot >> 3, q = slot & 7;
                pbh[p] = *(const uint4*)(g_Wvh + (size_t)e*4096 + (i+1)*64 + q*8);
                pbl[p] = *(const uint4*)(g_Wvl + (size_t)e*4096 + (i+1)*64 + q*8);
            }
        }
        const __nv_bfloat16* cBh = sB + cur*64*SV;
        const __nv_bfloat16* cBl = sB + (2 + cur)*64*SV;

        float tacc[2][4][4];
#pragma unroll
        for (int mt = 0; mt < 2; mt++)
#pragma unroll
            for (int ntl = 0; ntl < 4; ntl++)
#pragma unroll
                for (int j = 0; j < 4; j++) tacc[mt][ntl][j] = 0.f;

#pragma unroll
        for (int ks = 0; ks < 4; ks++) {
            int k0 = ks << 4;
            unsigned bhf[4][2], blf[4][2];
#pragma unroll
            for (int ntl = 0; ntl < 4; ntl++) {
                const __nv_bfloat16* p0 = cBh + (wn + ntl*8 + gm)*SV + k0 + kp;
                const __nv_bfloat16* p1 = cBl + (wn + ntl*8 + gm)*SV + k0 + kp;
                bhf[ntl][0] = *(const unsigned*)(p0);
                bhf[ntl][1] = *(const unsigned*)(p0 + 8);
                blf[ntl][0] = *(const unsigned*)(p1);
                blf[ntl][1] = *(const unsigned*)(p1 + 8);
            }
#pragma unroll
            for (int mt = 0; mt < 2; mt++)
#pragma unroll
                for (int ntl = 0; ntl < 4; ntl++) {
                    float* cp = tacc[mt][ntl];
                    mma16816(cp, vh[ks][mt], bhf[ntl]);
                    mma16816(cp, vh[ks][mt], blf[ntl]);
                    mma16816(cp, vl[ks][mt], bhf[ntl]);
                }
        }
        // fold k[t,i] in fp32
#pragma unroll
        for (int mt = 0; mt < 2; mt++) {
            float k0v = sk[(wm + mt*16 + gm)*SKP + i];
            float k1v = sk[(wm + mt*16 + gm + 8)*SKP + i];
#pragma unroll
            for (int ntl = 0; ntl < 4; ntl++) {
                acc[mt][ntl][0] += k0v * tacc[mt][ntl][0];
                acc[mt][ntl][1] += k0v * tacc[mt][ntl][1];
                acc[mt][ntl][2] += k1v * tacc[mt][ntl][2];
                acc[mt][ntl][3] += k1v * tacc[mt][ntl][3];
            }
        }
        // stage B(i+1) into nxt buffer
        if (i + 1 < 64) {
            __nv_bfloat16* dBh = sB + nxt*64*SV;
            __nv_bfloat16* dBl = sB + (2 + nxt)*64*SV;
#pragma unroll
            for (int p = 0; p < 2; p++) {
                int slot = tid + p*256;
                int e = slot >> 3, q = slot & 7;
                *(uint4*)(dBh + e*SV + q*8) = pbh[p];
                *(uint4*)(dBl + e*SV + q*8) = pbl[p];
            }
            __syncthreads();
        }
    }

    float* vout = g_v + ((size_t)bh*TT + t0)*HS;
    int col = wn + (lane & 3)*2;
#pragma unroll
    for (int mt = 0; mt < 2; mt++) {
        int row = wm + mt*16 + gm;
#pragma unroll
        for (int ntl = 0; ntl < 4; ntl++) {
            int c = col + ntl*8;
            float b0 = bv[c], b1 = bv[c+1];
            *(float2*)(vout + (size_t)row*HS + c) =
                make_float2(acc[mt][ntl][0] + b0, acc[mt][ntl][1] + b1);
            *(float2*)(vout + (size_t)(row+8)*HS + c) =
                make_float2(acc[mt][ntl][2] + b0, acc[mt][ntl][3] + b1);
        }
    }
}

// ---------------- cumsum / slices / attention (unchanged, passing) ---------
__global__ void cumsum_partial() {
    int chunk = blockIdx.x, bh = blockIdx.y, which = blockIdx.z;
    int d = threadIdx.x;
    int b = bh / NHH, h = bh - b*NHH;
    float s = 0.f;
    if (which == 0) {
        const float* p = g_qkv + ((size_t)(b*TT + (chunk<<7)))*C3 + CC + h*HS + d;
#pragma unroll 4
        for (int t2 = 0; t2 < 128; t2++) s += p[(size_t)t2*C3];
    } else {
        const float* p = g_v + ((size_t)bh*TT + (chunk<<7))*HS + d;
#pragma unroll 4
        for (int t2 = 0; t2 < 128; t2++) s += p[t2*HS];
    }
    g_part[((size_t)(which*BHC + bh)*NCHUNK + chunk)*HS + d] = s;
}

__global__ void cumsum_scanpart() {
    int bh = blockIdx.x, which = blockIdx.y;
    int d = threadIdx.x;
    float run = 0.f;
    for (int c = 0; c < NCHUNK; c++) {
        size_t idx = ((size_t)(which*BHC + bh)*NCHUNK + c)*HS + d;
        float xv = g_part[idx];
        g_part[idx] = run;
        run += xv;
    }
}

__global__ void cumsum_final() {
    int chunk = blockIdx.x, bh = blockIdx.y, which = blockIdx.z;
    int d = threadIdx.x;
    int b = bh / NHH, h = bh - b*NHH;
    float run = g_part[((size_t)(which*BHC + bh)*NCHUNK + chunk)*HS + d];
    float* outp = (which ? g_vc : g_kc) + ((size_t)bh*TT + (chunk<<7))*HS + d;
    if (which == 0) {
        const float* p = g_qkv + ((size_t)(b*TT + (chunk<<7)))*C3 + CC + h*HS + d;
#pragma unroll 4
        for (int t2 = 0; t2 < 128; t2++) { run += p[(size_t)t2*C3]; outp[(size_t)t2*HS] = run; }
    } else {
        const float* p = g_v + ((size_t)bh*TT + (chunk<<7))*HS + d;
#pragma unroll 4
        for (int t2 = 0; t2 < 128; t2++) { run += p[t2*HS]; outp[(size_t)t2*HS] = run; }
    }
}

__global__ void slices_kernel() {
    int bh = blockIdx.x;
    const float* kcb = g_kc + (size_t)bh*TT*HS;
    const float* vcb = g_vc + (size_t)bh*TT*HS;
    for (int idx = threadIdx.x; idx < NSI*HS; idx += 256) {
        int s = idx / HS, d = idx - s*HS;
        int l, r; interval_of(s, l, r);
        float kv = kcb[(size_t)r*HS + d];
        float vv = vcb[(size_t)r*HS + d];
        if (l > 0) { kv -= kcb[(size_t)(l-1)*HS + d]; vv -= vcb[(size_t)(l-1)*HS + d]; }
        g_Ki[(size_t)bh*NSI*HS + idx] = kv;
        g_Vi[(size_t)bh*NSI*HS + idx] = vv;
    }
}

__global__ __launch_bounds__(256) void attention_kernel() {
    extern __shared__ float sm[];
    float* Ks = sm;
    float* Vs = sm + NSI*HS;
    const int bh = blockIdx.y;
    const int b = bh / NHH, h = bh - b*NHH;
    const int tid = threadIdx.x;
    const int t = (blockIdx.x << 8) + tid;

    const float* Kgb = g_Ki + (size_t)bh*NSI*HS;
    const float* Vgb = g_Vi + (size_t)bh*NSI*HS;
    for (int idx = tid*4; idx < NSI*HS; idx += 1024) {
        *(float4*)(Ks + idx) = *(const float4*)(Kgb + idx);
        *(float4*)(Vs + idx) = *(const float4*)(Vgb + idx);
    }
    __syncthreads();

    float q[64];
    const float* qp = g_qkv + ((size_t)(b*TT + t))*C3 + h*HS;
#pragma unroll
    for (int d4 = 0; d4 < 16; d4++) {
        float4 qq = *(const float4*)(qp + d4*4);
        q[d4*4+0]=qq.x; q[d4*4+1]=qq.y; q[d4*4+2]=qq.z; q[d4*4+3]=qq.w;
    }
    float out[64];
#pragma unroll
    for (int d = 0; d < 64; d++) out[d] = 0.f;
    float m = -1e30f, ssum = 0.f;
    const float scale = 0.125f;
    const int twmax = t | 31;

    int sbase = 0;
#pragma unroll 1
    for (int lev = 0; lev < 8; lev++) {
        const int lsh = 4 + lev;
        const int n = TT >> lsh;
        int imaxw = (twmax + 1) >> lsh;
        if (imaxw > n) imaxw = n;
        for (int i = 0; i < imaxw; i++) {
            const int s = sbase + i;
            const int r = ((i + 1) << lsh) - 1;
            const float* Kr = Ks + s*HS;
            float a0=0.f, a1=0.f, a2=0.f, a3=0.f;
#pragma unroll
            for (int d4 = 0; d4 < 16; d4++) {
                float4 kv = *(const float4*)(Kr + d4*4);
                a0 += q[d4*4+0]*kv.x; a1 += q[d4*4+1]*kv.y;
                a2 += q[d4*4+2]*kv.z; a3 += q[d4*4+3]*kv.w;
            }
            float x = (a0+a1+a2+a3) * scale;
            if (t >= r) {
                const float* Vr = Vs + s*HS;
                if (x > m) {
                    float f = __expf(m - x);
                    ssum = ssum * f + 1.f;
                    m = x;
#pragma unroll
                    for (int d4 = 0; d4 < 16; d4++) {
                        float4 vv = *(const float4*)(Vr + d4*4);
                        out[d4*4+0] = out[d4*4+0]*f + vv.x;
                        out[d4*4+1] = out[d4*4+1]*f + vv.y;
                        out[d4*4+2] = out[d4*4+2]*f + vv.z;
                        out[d4*4+3] = out[d4*4+3]*f + vv.w;
                    }
                } else {
                    float wgt = __expf(x - m);
                    ssum += wgt;
#pragma unroll
                    for (int d4 = 0; d4 < 16; d4++) {
                        float4 vv = *(const float4*)(Vr + d4*4);
                        out[d4*4+0] += wgt*vv.x; out[d4*4+1] += wgt*vv.y;
                        out[d4*4+2] += wgt*vv.z; out[d4*4+3] += wgt*vv.w;
                    }
                }
            }
        }
        sbase += n;
    }

    const int lt = t & ~15;
    const bool hasl = lt > 0;
    const float* kr = g_kc + ((size_t)bh*TT + t)*HS;
    const float* kl = g_kc + ((size_t)bh*TT + (hasl ? lt-1 : 0))*HS;
    const float* vr = g_vc + ((size_t)bh*TT + t)*HS;
    const float* vl = g_vc + ((size_t)bh*TT + (hasl ? lt-1 : 0))*HS;
    float a0=0.f, a1=0.f, a2=0.f, a3=0.f;
#pragma unroll
    for (int d4 = 0; d4 < 16; d4++) {
        float4 kv = *(const float4*)(kr + d4*4);
        float4 klv = hasl ? *(const float4*)(kl + d4*4) : make_float4(0.f,0.f,0.f,0.f);
        a0 += q[d4*4+0]*(kv.x-klv.x); a1 += q[d4*4+1]*(kv.y-klv.y);
        a2 += q[d4*4+2]*(kv.z-klv.z); a3 += q[d4*4+3]*(kv.w-klv.w);
    }
    float xt = (a0+a1+a2+a3) * scale;
    if (xt > m) {
        float f = __expf(m - xt);
        ssum = ssum * f + 1.f;
        m = xt;
#pragma unroll
        for (int d4 = 0; d4 < 16; d4++) {
            float4 vv = *(const float4*)(vr + d4*4);
            float4 vlv = hasl ? *(const float4*)(vl + d4*4) : make_float4(0.f,0.f,0.f,0.f);
            out[d4*4+0] = out[d4*4+0]*f + (vv.x-vlv.x);
            out[d4*4+1] = out[d4*4+1]*f + (vv.y-vlv.y);
            out[d4*4+2] = out[d4*4+2]*f + (vv.z-vlv.z);
            out[d4*4+3] = out[d4*4+3]*f + (vv.w-vlv.w);
        }
    } else {
        float wgt = __expf(xt - m);
        ssum += wgt;
#pragma unroll
        for (int d4 = 0; d4 < 16; d4++) {
            float4 vv = *(const float4*)(vr + d4*4);
            float4 vlv = hasl ? *(const float4*)(vl + d4*4) : make_float4(0.f,0.f,0.f,0.f);
            out[d4*4+0] += wgt*(vv.x-vlv.x); out[d4*4+1] += wgt*(vv.y-vlv.y);
            out[d4*4+2] += wgt*(vv.z-vlv.z); out[d4*4+3] += wgt*(vv.w-vlv.w);
        }
    }

    float inv = 1.f / ssum;
    float* op = g_att + ((size_t)(b*TT + t))*CC + h*HS;
#pragma unroll
    for (int d4 = 0; d4 < 16; d4++) {
        *(float4*)(op + d4*4) = make_float4(out[d4*4+0]*inv, out[d4*4+1]*inv,
                                            out[d4*4+2]*inv, out[d4*4+3]*inv);
    }
}

extern "C" void kernel_launch(void* const* d_in, const int* in_sizes, int n_in,
                              void* d_out, int out_size) {
    (void)in_sizes; (void)n_in; (void)out_size;
    const float* x     = (const float*)d_in[0];
    const float* Wqkv  = (const float*)d_in[1];
    const float* Wproj = (const float*)d_in[2];
    const float* Wv    = (const float*)d_in[3];
    const float* bv    = (const float*)d_in[4];
    float* out = (float*)d_out;

    static bool attr_set = false;
    if (!attr_set) {
        cudaFuncSetAttribute(veinsum_mma,
            cudaFuncAttributeMaxDynamicSharedMemorySize, 107008);
        cudaFuncSetAttribute(attention_kernel,
            cudaFuncAttributeMaxDynamicSharedMemorySize, 130560);
        attr_set = true;
    }

    float* qkv;  cudaGetSymbolAddress((void**)&qkv, g_qkv);
    float* gatt; cudaGetSymbolAddress((void**)&gatt, g_att);

    // 0. split Wv into bf16 hi/lo
    wvsplit_kernel<<<1024, 256>>>(Wv);

    // 1. QKV GEMM: (16384,768) @ (2304,768)^T -> (16384,2304)
    gemm_tn_mma<<<dim3(18, 128), 256>>>(x, Wqkv, qkv, 16384, 2304, 768);

    // 2. fused v-einsum (tensor cores, k folded in fp32)
    veinsum_mma<<<dim3(16, BHC), 256, 107008>>>(bv);

    // 3. cumsum
    cumsum_partial <<<dim3(NCHUNK, BHC, 2), 64>>>();
    cumsum_scanpart<<<dim3(BHC, 2), 64>>>();
    cumsum_final   <<<dim3(NCHUNK, BHC, 2), 64>>>();

    // 4. interval slices
    slices_kernel<<<BHC, 256>>>();

    // 5. attention
    attention_kernel<<<dim3(8, BHC), 256, 130560>>>();

    // 6. output projection: (16384,768) @ (768,768)^T -> (16384,768)
    gemm_tn_mma<<<dim3(6, 128), 256>>>(gatt, Wproj, out, 16384, 768, 768);
}